// round 11
// baseline (speedup 1.0000x reference)
#include <cuda_runtime.h>
#include <cuda_bf16.h>
#include <cstdint>

#define HEADS 6
#define NTOK  64
#define DIM   96
#define NW    512

typedef uint32_t u32;

// ---------------- bf16 split-pack: f32 pair -> (hi pair, lo pair) ----------------
__device__ __forceinline__ void bsplit2(float f0, float f1, u32& hi, u32& lo) {
    __nv_bfloat162 h = __floats2bfloat162_rn(f0, f1);
    float r0 = f0 - __bfloat162float(h.x);
    float r1 = f1 - __bfloat162float(h.y);
    __nv_bfloat162 l = __floats2bfloat162_rn(r0, r1);
    hi = ((u32)__bfloat16_as_ushort(h.y) << 16) | __bfloat16_as_ushort(h.x);
    lo = ((u32)__bfloat16_as_ushort(l.y) << 16) | __bfloat16_as_ushort(l.x);
}

// mma.m16n8k16 row.col f32 += bf16*bf16
__device__ __forceinline__ void mma16816(float* d, const u32* a, u32 b0, u32 b1) {
    asm volatile("mma.sync.aligned.m16n8k16.row.col.f32.bf16.bf16.f32 "
        "{%0,%1,%2,%3}, {%4,%5,%6,%7}, {%8,%9}, {%0,%1,%2,%3};"
        : "+f"(d[0]), "+f"(d[1]), "+f"(d[2]), "+f"(d[3])
        : "r"(a[0]), "r"(a[1]), "r"(a[2]), "r"(a[3]), "r"(b0), "r"(b1));
}
__device__ __forceinline__ void ldmx4(u32* r, u32 addr) {
    asm volatile("ldmatrix.sync.aligned.m8n8.x4.shared.b16 {%0,%1,%2,%3}, [%4];"
        : "=r"(r[0]), "=r"(r[1]), "=r"(r[2]), "=r"(r[3]) : "r"(addr));
}
__device__ __forceinline__ void ldmx4t(u32* r, u32 addr) {
    asm volatile("ldmatrix.sync.aligned.m8n8.x4.trans.shared.b16 {%0,%1,%2,%3}, [%4];"
        : "=r"(r[0]), "=r"(r[1]), "=r"(r[2]), "=r"(r[3]) : "r"(addr));
}
__device__ __forceinline__ u32 smem_u32(const void* p) {
    u32 a; asm("{ .reg .u64 t; cvta.to.shared.u64 t, %1; cvt.u32.u64 %0, t; }"
               : "=r"(a) : "l"(p)); return a;
}

// Combined (rpb-gather + shift-mask) table: [w][h][n][m] fp32, ~50MB.
__device__ float cmb[NW * HEADS * NTOK * NTOK];

__global__ void prep_kernel(const float* __restrict__ rpb,
                            const int* __restrict__ ridx,
                            const float* __restrict__ mask) {
    int i = blockIdx.x * 256 + threadIdx.x;
    if (i >= NW * HEADS * NTOK * NTOK) return;
    int w = i / (HEADS * 4096), rem = i % (HEADS * 4096);
    cmb[i] = rpb[ridx[rem % 4096] * HEADS + rem / 4096] + mask[w * 4096 + rem % 4096];
}

// ---------------- SMEM layout (bytes); 208B row stride, 1 window/CTA ----------
// RQ @ 0     : x staging (hi/lo) -> overwritten by Q (hi/lo)      2x13312
// K  @ 26624 : K hi/lo                                            2x13312
// V  @ 53248 : V hi/lo                                            2x13312
// OW @ 79872 : W staging (WH @ +0 6656, WL @ +6656 6656) in GEMM phases;
//              O hi @ +0 / lo @ +13312 between phase 2 and 3      2x13312
#define RQ_B 0
#define KB_B 26624
#define VB_B 53248
#define OW_B 79872
#define HL   13312            // (lo - hi) offset inside each region
#define WLOF 6656             // WL - WH inside OW region
#define SMEM_BYTES 106496

__global__ __launch_bounds__(256, 2)
void win_attn_kernel(const float* __restrict__ x,
                     const float* __restrict__ qkv_w,
                     const float* __restrict__ qkv_b,
                     const float* __restrict__ proj_w,
                     const float* __restrict__ proj_b,
                     float* __restrict__ out)
{
    extern __shared__ char smc[];
    const int tid  = threadIdx.x;
    const int lane = tid & 31;
    const int wid  = tid >> 5;            // 0..7
    const int m    = wid & 3;             // GEMM M-tile (16 rows of 64)
    const int nh   = wid >> 2;            // GEMM N-half of 32-col chunk

    const u32 sb = smem_u32(smc);
    const int lrow  = (lane & 7) + 8 * ((lane >> 3) & 1);
    const int lkoff = (lane >> 4) * 16;
    const u32 a_h = sb + RQ_B + (u32)(m * 16 + lrow) * 208 + lkoff;   // x / Q rows
    const u32 a_l = a_h + HL;
    const u32 b_h = sb + OW_B + (u32)(nh * 16 + lrow) * 208 + lkoff;  // W rows
    const u32 b_l = b_h + WLOF;

    // staging-thread indices: 1536 (n,k2) entries over 256 threads
    int se_n[6], se_k2[6];
    #pragma unroll
    for (int u = 0; u < 6; ++u) { se_n[u] = (tid + u * 256) & 31; se_k2[u] = (tid + u * 256) >> 5; }

    // ---- prefetch qkv_w chunk 0 ----
    float wv0[6], wv1[6];
    #pragma unroll
    for (int u = 0; u < 6; ++u) {
        wv0[u] = qkv_w[(size_t)(2 * se_k2[u]) * 288 + se_n[u]];
        wv1[u] = qkv_w[(size_t)(2 * se_k2[u] + 1) * 288 + se_n[u]];
    }

    // ================= phase 0: load x (64x96) into RQ, split-pack ==============
    {
        const float4* xg = reinterpret_cast<const float4*>(x + (size_t)blockIdx.x * 64 * 96);
        #pragma unroll
        for (int u = 0; u < 6; ++u) {
            int e = tid + u * 256;                 // 1536 float4
            float4 v = xg[e];
            int tok = e / 24, c4 = (e % 24) * 4;
            u32 h0, l0, h1, l1;
            bsplit2(v.x, v.y, h0, l0);
            bsplit2(v.z, v.w, h1, l1);
            *reinterpret_cast<uint2*>(smc + RQ_B + tok * 208 + c4 * 2)      = make_uint2(h0, h1);
            *reinterpret_cast<uint2*>(smc + RQ_B + HL + tok * 208 + c4 * 2) = make_uint2(l0, l1);
        }
    }
    __syncthreads();

    // ---- x A-fragments into registers (RQ region then becomes dead -> Q) ----
    u32 xah[6][4], xal[6][4];
    #pragma unroll
    for (int ks = 0; ks < 6; ++ks) {
        ldmx4(xah[ks], a_h + ks * 32);
        ldmx4(xal[ks], a_l + ks * 32);
    }

    // ================= phase 1: QKV GEMM, 9 chunks of N=32, bf16x3 ==============
    #pragma unroll 1
    for (int c = 0; c < 9; ++c) {
        if (c) __syncthreads();          // prev chunk's B ldmatrix reads done
        #pragma unroll
        for (int u = 0; u < 6; ++u) {    // STS staged W chunk from regs
            u32 hi, lo; bsplit2(wv0[u], wv1[u], hi, lo);
            *reinterpret_cast<u32*>(smc + OW_B + se_n[u] * 208 + se_k2[u] * 4)        = hi;
            *reinterpret_cast<u32*>(smc + OW_B + WLOF + se_n[u] * 208 + se_k2[u] * 4) = lo;
        }
        __syncthreads();
        if (c < 8) {                     // prefetch next chunk (overlaps MMA)
            #pragma unroll
            for (int u = 0; u < 6; ++u) {
                wv0[u] = qkv_w[(size_t)(2 * se_k2[u]) * 288 + (c + 1) * 32 + se_n[u]];
                wv1[u] = qkv_w[(size_t)(2 * se_k2[u] + 1) * 288 + (c + 1) * 32 + se_n[u]];
            }
        }

        float d[2][4] = {{0.f,0.f,0.f,0.f},{0.f,0.f,0.f,0.f}};
        #pragma unroll
        for (int ks = 0; ks < 6; ++ks) {
            u32 bh[4], bl[4];
            ldmx4(bh, b_h + ks * 32);
            ldmx4(bl, b_l + ks * 32);
            mma16816(d[0], xah[ks], bh[0], bh[2]);
            mma16816(d[0], xah[ks], bl[0], bl[2]);
            mma16816(d[0], xal[ks], bh[0], bh[2]);
            mma16816(d[1], xah[ks], bh[1], bh[3]);
            mma16816(d[1], xah[ks], bl[1], bl[3]);
            mma16816(d[1], xal[ks], bh[1], bh[3]);
        }

        // epilogue: +bias (Q also *0.25), split-pack into RQ/K/V [tok][ch pairs]
        const int p = c / 3;
        const int base_h = (p == 0) ? RQ_B : (p == 1) ? KB_B : VB_B;
        const int tk = m * 16 + (lane >> 2);
        char* outh = smc + base_h + tk * 208;
        char* outl = outh + HL;
        #pragma unroll
        for (int nt = 0; nt < 2; ++nt) {
            int g = c * 32 + nh * 16 + nt * 8 + 2 * (lane & 3);
            int ch = g % 96;
            float bb0 = qkv_b[g], bb1 = qkv_b[g + 1];
            float v00 = d[nt][0] + bb0, v01 = d[nt][1] + bb1;
            float v10 = d[nt][2] + bb0, v11 = d[nt][3] + bb1;
            if (p == 0) { v00 *= 0.25f; v01 *= 0.25f; v10 *= 0.25f; v11 *= 0.25f; }
            u32 hh, ll;
            bsplit2(v00, v01, hh, ll);
            *reinterpret_cast<u32*>(outh + (ch >> 1) * 4) = hh;
            *reinterpret_cast<u32*>(outl + (ch >> 1) * 4) = ll;
            bsplit2(v10, v11, hh, ll);
            *reinterpret_cast<u32*>(outh + 8 * 208 + (ch >> 1) * 4) = hh;
            *reinterpret_cast<u32*>(outl + 8 * 208 + (ch >> 1) * 4) = ll;
        }
    }
    __syncthreads();

    // ================= phase 2: attention, all-MMA, softmax in registers ========
    {
        const int hsub = wid >> 2;            // head parity
        const int mt   = wid & 3;             // 16-row q tile
        const int r    = mt * 16 + (lane >> 2);
        const float* cw = cmb + (size_t)(blockIdx.x & (NW - 1)) * (HEADS * 4096);
        const u32 qbase = sb + RQ_B + (u32)(mt * 16 + lrow) * 208 + lkoff;
        const u32 kbase = sb + KB_B + (u32)lrow * 208 + lkoff;
        const u32 vbase = sb + VB_B + (u32)lrow * 208 + lkoff;
        char* ooh = smc + OW_B + (mt * 16 + (lane >> 2)) * 208;
        char* ool = ooh + HL;

        #pragma unroll 1
        for (int hi2 = 0; hi2 < 3; ++hi2) {
            const int h = 2 * hi2 + hsub;
            const u32 chb = h * 32;

            u32 qh4[4], ql4[4];
            ldmx4(qh4, qbase + chb);
            ldmx4(ql4, qbase + HL + chb);

            float d[8][4];
            const float* cm = cw + h * 4096 + 2 * (lane & 3);
            #pragma unroll
            for (int j = 0; j < 8; ++j) {
                float2 c0 = *reinterpret_cast<const float2*>(&cm[r * 64 + 8 * j]);
                float2 c1 = *reinterpret_cast<const float2*>(&cm[(r + 8) * 64 + 8 * j]);
                d[j][0] = c0.x; d[j][1] = c0.y; d[j][2] = c1.x; d[j][3] = c1.y;
            }
            #pragma unroll
            for (int t = 0; t < 4; ++t) {
                u32 kh4[4], kl4[4];
                ldmx4(kh4, kbase + t * (16 * 208) + chb);
                ldmx4(kl4, kbase + HL + t * (16 * 208) + chb);
                mma16816(d[2 * t],     qh4, kh4[0], kh4[2]);
                mma16816(d[2 * t],     qh4, kl4[0], kl4[2]);
                mma16816(d[2 * t],     ql4, kh4[0], kh4[2]);
                mma16816(d[2 * t + 1], qh4, kh4[1], kh4[3]);
                mma16816(d[2 * t + 1], qh4, kl4[1], kl4[3]);
                mma16816(d[2 * t + 1], ql4, kh4[1], kh4[3]);
            }

            float mx0 = -1e30f, mx1 = -1e30f;
            #pragma unroll
            for (int j = 0; j < 8; ++j) {
                mx0 = fmaxf(mx0, fmaxf(d[j][0], d[j][1]));
                mx1 = fmaxf(mx1, fmaxf(d[j][2], d[j][3]));
            }
            mx0 = fmaxf(mx0, __shfl_xor_sync(0xffffffffu, mx0, 1, 4));
            mx0 = fmaxf(mx0, __shfl_xor_sync(0xffffffffu, mx0, 2, 4));
            mx1 = fmaxf(mx1, __shfl_xor_sync(0xffffffffu, mx1, 1, 4));
            mx1 = fmaxf(mx1, __shfl_xor_sync(0xffffffffu, mx1, 2, 4));
            float s0 = 0.f, s1 = 0.f;
            #pragma unroll
            for (int j = 0; j < 8; ++j) {
                d[j][0] = __expf(d[j][0] - mx0); d[j][1] = __expf(d[j][1] - mx0);
                d[j][2] = __expf(d[j][2] - mx1); d[j][3] = __expf(d[j][3] - mx1);
                s0 += d[j][0] + d[j][1];
                s1 += d[j][2] + d[j][3];
            }
            s0 += __shfl_xor_sync(0xffffffffu, s0, 1, 4);
            s0 += __shfl_xor_sync(0xffffffffu, s0, 2, 4);
            s1 += __shfl_xor_sync(0xffffffffu, s1, 1, 4);
            s1 += __shfl_xor_sync(0xffffffffu, s1, 2, 4);
            const float inv0 = 1.0f / s0, inv1 = 1.0f / s1;

            float o0[4] = {0.f,0.f,0.f,0.f}, o1[4] = {0.f,0.f,0.f,0.f};
            #pragma unroll
            for (int ks = 0; ks < 4; ++ks) {
                u32 pah[4], pal[4];
                bsplit2(d[2*ks][0]   * inv0, d[2*ks][1]   * inv0, pah[0], pal[0]);
                bsplit2(d[2*ks][2]   * inv1, d[2*ks][3]   * inv1, pah[1], pal[1]);
                bsplit2(d[2*ks+1][0] * inv0, d[2*ks+1][1] * inv0, pah[2], pal[2]);
                bsplit2(d[2*ks+1][2] * inv1, d[2*ks+1][3] * inv1, pah[3], pal[3]);
                u32 vh4[4], vl4[4];
                ldmx4t(vh4, vbase + ks * (16 * 208) + chb);
                ldmx4t(vl4, vbase + HL + ks * (16 * 208) + chb);
                mma16816(o0, pah, vh4[0], vh4[1]);
                mma16816(o0, pah, vl4[0], vl4[1]);
                mma16816(o0, pal, vh4[0], vh4[1]);
                mma16816(o1, pah, vh4[2], vh4[3]);
                mma16816(o1, pah, vl4[2], vl4[3]);
                mma16816(o1, pal, vh4[2], vh4[3]);
            }

            {   // O into OW region (W is dead between phases 1 and 3)
                int ch0 = h * 16 + 2 * (lane & 3);
                u32 hh, ll;
                bsplit2(o0[0], o0[1], hh, ll);
                *reinterpret_cast<u32*>(ooh + (ch0 >> 1) * 4) = hh;
                *reinterpret_cast<u32*>(ool + (ch0 >> 1) * 4) = ll;
                bsplit2(o0[2], o0[3], hh, ll);
                *reinterpret_cast<u32*>(ooh + 8 * 208 + (ch0 >> 1) * 4) = hh;
                *reinterpret_cast<u32*>(ool + 8 * 208 + (ch0 >> 1) * 4) = ll;
                int ch1 = ch0 + 8;
                bsplit2(o1[0], o1[1], hh, ll);
                *reinterpret_cast<u32*>(ooh + (ch1 >> 1) * 4) = hh;
                *reinterpret_cast<u32*>(ool + (ch1 >> 1) * 4) = ll;
                bsplit2(o1[2], o1[3], hh, ll);
                *reinterpret_cast<u32*>(ooh + 8 * 208 + (ch1 >> 1) * 4) = hh;
                *reinterpret_cast<u32*>(ool + 8 * 208 + (ch1 >> 1) * 4) = ll;
            }
        }
    }

    // ---- prefetch proj_w chunk 0 ----
    float pw0[6], pw1[6];
    #pragma unroll
    for (int u = 0; u < 6; ++u) {
        pw0[u] = proj_w[(size_t)(2 * se_k2[u]) * 96 + se_n[u]];
        pw1[u] = proj_w[(size_t)(2 * se_k2[u] + 1) * 96 + se_n[u]];
    }
    __syncthreads();                      // all O writes visible

    // ---- O A-fragments into regs BEFORE W staging overwrites OW ----
    u32 oah[6][4], oal[6][4];
    {
        const u32 o_h = sb + OW_B + (u32)(m * 16 + lrow) * 208 + lkoff;
        #pragma unroll
        for (int ks = 0; ks < 6; ++ks) {
            ldmx4(oah[ks], o_h + ks * 32);
            ldmx4(oal[ks], o_h + HL + ks * 32);
        }
    }
    __syncthreads();                      // O reads done; OW safe to overwrite

    // ================= phase 3: proj GEMM, 3 chunks of N=32, bf16x3 =============
    #pragma unroll 1
    for (int pc = 0; pc < 3; ++pc) {
        if (pc) __syncthreads();
        #pragma unroll
        for (int u = 0; u < 6; ++u) {
            u32 hi, lo; bsplit2(pw0[u], pw1[u], hi, lo);
            *reinterpret_cast<u32*>(smc + OW_B + se_n[u] * 208 + se_k2[u] * 4)        = hi;
            *reinterpret_cast<u32*>(smc + OW_B + WLOF + se_n[u] * 208 + se_k2[u] * 4) = lo;
        }
        __syncthreads();
        if (pc < 2) {
            #pragma unroll
            for (int u = 0; u < 6; ++u) {
                pw0[u] = proj_w[(size_t)(2 * se_k2[u]) * 96 + (pc + 1) * 32 + se_n[u]];
                pw1[u] = proj_w[(size_t)(2 * se_k2[u] + 1) * 96 + (pc + 1) * 32 + se_n[u]];
            }
        }

        float d[2][4] = {{0.f,0.f,0.f,0.f},{0.f,0.f,0.f,0.f}};
        #pragma unroll
        for (int ks = 0; ks < 6; ++ks) {
            u32 bh[4], bl[4];
            ldmx4(bh, b_h + ks * 32);
            ldmx4(bl, b_l + ks * 32);
            mma16816(d[0], oah[ks], bh[0], bh[2]);
            mma16816(d[0], oah[ks], bl[0], bl[2]);
            mma16816(d[0], oal[ks], bh[0], bh[2]);
            mma16816(d[1], oah[ks], bh[1], bh[3]);
            mma16816(d[1], oah[ks], bl[1], bl[3]);
            mma16816(d[1], oal[ks], bh[1], bh[3]);
        }

        float* og = out + (size_t)blockIdx.x * 64 * 96;
        const int row0 = m * 16 + (lane >> 2);
        #pragma unroll
        for (int nt = 0; nt < 2; ++nt) {
            int g = pc * 32 + nh * 16 + nt * 8 + 2 * (lane & 3);
            float b0 = proj_b[g], b1 = proj_b[g + 1];
            float2 v0 = make_float2(d[nt][0] + b0, d[nt][1] + b1);
            float2 v1 = make_float2(d[nt][2] + b0, d[nt][3] + b1);
            *reinterpret_cast<float2*>(og + (size_t)row0 * 96 + g)       = v0;
            *reinterpret_cast<float2*>(og + (size_t)(row0 + 8) * 96 + g) = v1;
        }
    }
}

extern "C" void kernel_launch(void* const* d_in, const int* in_sizes, int n_in,
                              void* d_out, int out_size)
{
    const float* x      = (const float*)d_in[0];
    const float* mask   = (const float*)d_in[1];
    const float* qkv_w  = (const float*)d_in[2];
    const float* qkv_b  = (const float*)d_in[3];
    const float* proj_w = (const float*)d_in[4];
    const float* proj_b = (const float*)d_in[5];
    const float* rpb    = (const float*)d_in[6];
    const int*   ridx   = (const int*)d_in[7];
    float* out = (float*)d_out;

    const int n_windows = in_sizes[0] / (NTOK * DIM);   // 8192

    cudaFuncSetAttribute(win_attn_kernel,
                         cudaFuncAttributeMaxDynamicSharedMemorySize, SMEM_BYTES);

    const int total = NW * HEADS * NTOK * NTOK;
    prep_kernel<<<(total + 255) / 256, 256>>>(rpb, ridx, mask);
    win_attn_kernel<<<n_windows, 256, SMEM_BYTES>>>(
        x, qkv_w, qkv_b, proj_w, proj_b, out);
}

// round 12
// speedup vs baseline: 1.0100x; 1.0100x over previous
#include <cuda_runtime.h>
#include <cuda_bf16.h>
#include <cstdint>

#define HEADS 6
#define NTOK  64
#define DIM   96
#define NW    512

typedef uint32_t u32;

// ---------------- bf16 split-pack: f32 pair -> (hi pair, lo pair) ----------------
__device__ __forceinline__ void bsplit2(float f0, float f1, u32& hi, u32& lo) {
    __nv_bfloat162 h = __floats2bfloat162_rn(f0, f1);
    float r0 = f0 - __bfloat162float(h.x);
    float r1 = f1 - __bfloat162float(h.y);
    __nv_bfloat162 l = __floats2bfloat162_rn(r0, r1);
    hi = ((u32)__bfloat16_as_ushort(h.y) << 16) | __bfloat16_as_ushort(h.x);
    lo = ((u32)__bfloat16_as_ushort(l.y) << 16) | __bfloat16_as_ushort(l.x);
}

// mma.m16n8k16 row.col f32 += bf16*bf16
__device__ __forceinline__ void mma16816(float* d, const u32* a, u32 b0, u32 b1) {
    asm volatile("mma.sync.aligned.m16n8k16.row.col.f32.bf16.bf16.f32 "
        "{%0,%1,%2,%3}, {%4,%5,%6,%7}, {%8,%9}, {%0,%1,%2,%3};"
        : "+f"(d[0]), "+f"(d[1]), "+f"(d[2]), "+f"(d[3])
        : "r"(a[0]), "r"(a[1]), "r"(a[2]), "r"(a[3]), "r"(b0), "r"(b1));
}
__device__ __forceinline__ void ldmx4(u32* r, u32 addr) {
    asm volatile("ldmatrix.sync.aligned.m8n8.x4.shared.b16 {%0,%1,%2,%3}, [%4];"
        : "=r"(r[0]), "=r"(r[1]), "=r"(r[2]), "=r"(r[3]) : "r"(addr));
}
__device__ __forceinline__ void ldmx4t(u32* r, u32 addr) {
    asm volatile("ldmatrix.sync.aligned.m8n8.x4.trans.shared.b16 {%0,%1,%2,%3}, [%4];"
        : "=r"(r[0]), "=r"(r[1]), "=r"(r[2]), "=r"(r[3]) : "r"(addr));
}
__device__ __forceinline__ u32 smem_u32(const void* p) {
    u32 a; asm("{ .reg .u64 t; cvta.to.shared.u64 t, %1; cvt.u32.u64 %0, t; }"
               : "=r"(a) : "l"(p)); return a;
}

// Combined (rpb-gather + shift-mask) table: [w][h][n][m] fp32, ~50MB.
__device__ float cmb[NW * HEADS * NTOK * NTOK];

__global__ void prep_kernel(const float* __restrict__ rpb,
                            const int* __restrict__ ridx,
                            const float* __restrict__ mask) {
    int i = blockIdx.x * 256 + threadIdx.x;
    if (i >= NW * HEADS * NTOK * NTOK) return;
    int w = i / (HEADS * 4096), rem = i % (HEADS * 4096);
    cmb[i] = rpb[ridx[rem % 4096] * HEADS + rem / 4096] + mask[w * 4096 + rem % 4096];
}

// ---------------- SMEM layout (bytes); 208B row stride, 1 window/CTA ----------
// RQ @ 0     : x staging (hi/lo) -> overwritten by Q (hi/lo)      2x13312
// K  @ 26624 : K hi/lo                                            2x13312
// V  @ 53248 : V hi/lo                                            2x13312
// OW @ 79872 : GEMM phases: DOUBLE-BUFFERED W staging
//                buf0 @ +0 (WH +0, WL +6656), buf1 @ +13312 (same inner layout)
//              between phases 2 and 3: O hi @ +0 / lo @ +13312
#define RQ_B 0
#define KB_B 26624
#define VB_B 53248
#define OW_B 79872
#define HL   13312            // (lo - hi) offset inside each region / W buf stride
#define WLOF 6656             // WL - WH inside a W buffer
#define SMEM_BYTES 106496

__global__ __launch_bounds__(256, 2)
void win_attn_kernel(const float* __restrict__ x,
                     const float* __restrict__ qkv_w,
                     const float* __restrict__ qkv_b,
                     const float* __restrict__ proj_w,
                     const float* __restrict__ proj_b,
                     float* __restrict__ out)
{
    extern __shared__ char smc[];
    const int tid  = threadIdx.x;
    const int lane = tid & 31;
    const int wid  = tid >> 5;            // 0..7
    const int m    = wid & 3;             // GEMM M-tile (16 rows of 64)
    const int nh   = wid >> 2;            // GEMM N-half of 32-col chunk

    const u32 sb = smem_u32(smc);
    const int lrow  = (lane & 7) + 8 * ((lane >> 3) & 1);
    const int lkoff = (lane >> 4) * 16;
    const u32 a_h  = sb + RQ_B + (u32)(m * 16 + lrow) * 208 + lkoff;   // x / Q rows
    const u32 a_l  = a_h + HL;
    const u32 b_h0 = sb + OW_B + (u32)(nh * 16 + lrow) * 208 + lkoff;  // W rows (buf0)

    // staging-thread indices: 1536 (n,k2) entries over 256 threads
    int se_n[6], se_k2[6];
    #pragma unroll
    for (int u = 0; u < 6; ++u) { se_n[u] = (tid + u * 256) & 31; se_k2[u] = (tid + u * 256) >> 5; }

    // ---- prefetch qkv_w chunk 0 ----
    float wv0[6], wv1[6];
    #pragma unroll
    for (int u = 0; u < 6; ++u) {
        wv0[u] = qkv_w[(size_t)(2 * se_k2[u]) * 288 + se_n[u]];
        wv1[u] = qkv_w[(size_t)(2 * se_k2[u] + 1) * 288 + se_n[u]];
    }

    // ================= phase 0: load x (64x96) into RQ, split-pack ==============
    {
        const float4* xg = reinterpret_cast<const float4*>(x + (size_t)blockIdx.x * 64 * 96);
        #pragma unroll
        for (int u = 0; u < 6; ++u) {
            int e = tid + u * 256;                 // 1536 float4
            float4 v = xg[e];
            int tok = e / 24, c4 = (e % 24) * 4;
            u32 h0, l0, h1, l1;
            bsplit2(v.x, v.y, h0, l0);
            bsplit2(v.z, v.w, h1, l1);
            *reinterpret_cast<uint2*>(smc + RQ_B + tok * 208 + c4 * 2)      = make_uint2(h0, h1);
            *reinterpret_cast<uint2*>(smc + RQ_B + HL + tok * 208 + c4 * 2) = make_uint2(l0, l1);
        }
    }
    __syncthreads();

    // ---- x A-fragments into registers (RQ region then becomes dead -> Q) ----
    u32 xah[6][4], xal[6][4];
    #pragma unroll
    for (int ks = 0; ks < 6; ++ks) {
        ldmx4(xah[ks], a_h + ks * 32);
        ldmx4(xal[ks], a_l + ks * 32);
    }

    // ---- stage W chunk 0 into buf0, prefetch chunk 1 ----
    #pragma unroll
    for (int u = 0; u < 6; ++u) {
        u32 hi, lo; bsplit2(wv0[u], wv1[u], hi, lo);
        *reinterpret_cast<u32*>(smc + OW_B + se_n[u] * 208 + se_k2[u] * 4)        = hi;
        *reinterpret_cast<u32*>(smc + OW_B + WLOF + se_n[u] * 208 + se_k2[u] * 4) = lo;
    }
    #pragma unroll
    for (int u = 0; u < 6; ++u) {
        wv0[u] = qkv_w[(size_t)(2 * se_k2[u]) * 288 + 32 + se_n[u]];
        wv1[u] = qkv_w[(size_t)(2 * se_k2[u] + 1) * 288 + 32 + se_n[u]];
    }
    __syncthreads();

    // ================= phase 1: QKV GEMM, 9 chunks, double-buffered W ===========
    #pragma unroll 1
    for (int c = 0; c < 9; ++c) {
        const u32 bb_h = b_h0 + ((c & 1) ? HL : 0);
        const u32 bb_l = bb_h + WLOF;
        // stage chunk c+1 into the other buffer (overlaps with this chunk's MMAs)
        if (c < 8) {
            const int bofs = ((c + 1) & 1) ? HL : 0;
            #pragma unroll
            for (int u = 0; u < 6; ++u) {
                u32 hi, lo; bsplit2(wv0[u], wv1[u], hi, lo);
                *reinterpret_cast<u32*>(smc + OW_B + bofs + se_n[u] * 208 + se_k2[u] * 4)        = hi;
                *reinterpret_cast<u32*>(smc + OW_B + bofs + WLOF + se_n[u] * 208 + se_k2[u] * 4) = lo;
            }
        }
        if (c < 7) {
            #pragma unroll
            for (int u = 0; u < 6; ++u) {
                wv0[u] = qkv_w[(size_t)(2 * se_k2[u]) * 288 + (c + 2) * 32 + se_n[u]];
                wv1[u] = qkv_w[(size_t)(2 * se_k2[u] + 1) * 288 + (c + 2) * 32 + se_n[u]];
            }
        }

        float d[2][4] = {{0.f,0.f,0.f,0.f},{0.f,0.f,0.f,0.f}};
        #pragma unroll
        for (int ks = 0; ks < 6; ++ks) {
            u32 bh[4], bl[4];
            ldmx4(bh, bb_h + ks * 32);
            ldmx4(bl, bb_l + ks * 32);
            mma16816(d[0], xah[ks], bh[0], bh[2]);
            mma16816(d[0], xah[ks], bl[0], bl[2]);
            mma16816(d[0], xal[ks], bh[0], bh[2]);
            mma16816(d[1], xah[ks], bh[1], bh[3]);
            mma16816(d[1], xah[ks], bl[1], bl[3]);
            mma16816(d[1], xal[ks], bh[1], bh[3]);
        }

        // epilogue: +bias (Q also *0.25), split-pack into RQ/K/V [tok][ch pairs]
        const int p = c / 3;
        const int base_h = (p == 0) ? RQ_B : (p == 1) ? KB_B : VB_B;
        const int tk = m * 16 + (lane >> 2);
        char* outh = smc + base_h + tk * 208;
        char* outl = outh + HL;
        #pragma unroll
        for (int nt = 0; nt < 2; ++nt) {
            int g = c * 32 + nh * 16 + nt * 8 + 2 * (lane & 3);
            int ch = g % 96;
            float bb0 = qkv_b[g], bb1 = qkv_b[g + 1];
            float v00 = d[nt][0] + bb0, v01 = d[nt][1] + bb1;
            float v10 = d[nt][2] + bb0, v11 = d[nt][3] + bb1;
            if (p == 0) { v00 *= 0.25f; v01 *= 0.25f; v10 *= 0.25f; v11 *= 0.25f; }
            u32 hh, ll;
            bsplit2(v00, v01, hh, ll);
            *reinterpret_cast<u32*>(outh + (ch >> 1) * 4) = hh;
            *reinterpret_cast<u32*>(outl + (ch >> 1) * 4) = ll;
            bsplit2(v10, v11, hh, ll);
            *reinterpret_cast<u32*>(outh + 8 * 208 + (ch >> 1) * 4) = hh;
            *reinterpret_cast<u32*>(outl + 8 * 208 + (ch >> 1) * 4) = ll;
        }
        __syncthreads();   // readers of this chunk done AND chunk c+1 visible
    }

    // ================= phase 2: attention, all-MMA, softmax in registers ========
    {
        const int hsub = wid >> 2;            // head parity
        const int mt   = wid & 3;             // 16-row q tile
        const int r    = mt * 16 + (lane >> 2);
        const float* cw = cmb + (size_t)(blockIdx.x & (NW - 1)) * (HEADS * 4096);
        const u32 qbase = sb + RQ_B + (u32)(mt * 16 + lrow) * 208 + lkoff;
        const u32 kbase = sb + KB_B + (u32)lrow * 208 + lkoff;
        const u32 vbase = sb + VB_B + (u32)lrow * 208 + lkoff;
        char* ooh = smc + OW_B + (mt * 16 + (lane >> 2)) * 208;
        char* ool = ooh + HL;

        #pragma unroll 1
        for (int hi2 = 0; hi2 < 3; ++hi2) {
            const int h = 2 * hi2 + hsub;
            const u32 chb = h * 32;

            u32 qh4[4], ql4[4];
            ldmx4(qh4, qbase + chb);
            ldmx4(ql4, qbase + HL + chb);

            float d[8][4];
            const float* cm = cw + h * 4096 + 2 * (lane & 3);
            #pragma unroll
            for (int j = 0; j < 8; ++j) {
                float2 c0 = *reinterpret_cast<const float2*>(&cm[r * 64 + 8 * j]);
                float2 c1 = *reinterpret_cast<const float2*>(&cm[(r + 8) * 64 + 8 * j]);
                d[j][0] = c0.x; d[j][1] = c0.y; d[j][2] = c1.x; d[j][3] = c1.y;
            }
            #pragma unroll
            for (int t = 0; t < 4; ++t) {
                u32 kh4[4], kl4[4];
                ldmx4(kh4, kbase + t * (16 * 208) + chb);
                ldmx4(kl4, kbase + HL + t * (16 * 208) + chb);
                mma16816(d[2 * t],     qh4, kh4[0], kh4[2]);
                mma16816(d[2 * t],     qh4, kl4[0], kl4[2]);
                mma16816(d[2 * t],     ql4, kh4[0], kh4[2]);
                mma16816(d[2 * t + 1], qh4, kh4[1], kh4[3]);
                mma16816(d[2 * t + 1], qh4, kl4[1], kl4[3]);
                mma16816(d[2 * t + 1], ql4, kh4[1], kh4[3]);
            }

            // exp WITHOUT max-shift (logits are O(1); softmax is shift-invariant)
            float s0 = 0.f, s1 = 0.f;
            #pragma unroll
            for (int j = 0; j < 8; ++j) {
                d[j][0] = __expf(d[j][0]); d[j][1] = __expf(d[j][1]);
                d[j][2] = __expf(d[j][2]); d[j][3] = __expf(d[j][3]);
                s0 += d[j][0] + d[j][1];
                s1 += d[j][2] + d[j][3];
            }
            // row-sum reduction runs concurrently with PV (inv used only at end)
            s0 += __shfl_xor_sync(0xffffffffu, s0, 1, 4);
            s0 += __shfl_xor_sync(0xffffffffu, s0, 2, 4);
            s1 += __shfl_xor_sync(0xffffffffu, s1, 1, 4);
            s1 += __shfl_xor_sync(0xffffffffu, s1, 2, 4);
            const float inv0 = 1.0f / s0, inv1 = 1.0f / s1;

            // PV on UNNORMALIZED exp values
            float o0[4] = {0.f,0.f,0.f,0.f}, o1[4] = {0.f,0.f,0.f,0.f};
            #pragma unroll
            for (int ks = 0; ks < 4; ++ks) {
                u32 pah[4], pal[4];
                bsplit2(d[2*ks][0],   d[2*ks][1],   pah[0], pal[0]);
                bsplit2(d[2*ks][2],   d[2*ks][3],   pah[1], pal[1]);
                bsplit2(d[2*ks+1][0], d[2*ks+1][1], pah[2], pal[2]);
                bsplit2(d[2*ks+1][2], d[2*ks+1][3], pah[3], pal[3]);
                u32 vh4[4], vl4[4];
                ldmx4t(vh4, vbase + ks * (16 * 208) + chb);
                ldmx4t(vl4, vbase + HL + ks * (16 * 208) + chb);
                mma16816(o0, pah, vh4[0], vh4[1]);
                mma16816(o0, pah, vl4[0], vl4[1]);
                mma16816(o0, pal, vh4[0], vh4[1]);
                mma16816(o1, pah, vh4[2], vh4[3]);
                mma16816(o1, pah, vl4[2], vl4[3]);
                mma16816(o1, pal, vh4[2], vh4[3]);
            }

            {   // O into OW region, normalized here (rows r -> inv0, r+8 -> inv1)
                int ch0 = h * 16 + 2 * (lane & 3);
                u32 hh, ll;
                bsplit2(o0[0] * inv0, o0[1] * inv0, hh, ll);
                *reinterpret_cast<u32*>(ooh + (ch0 >> 1) * 4) = hh;
                *reinterpret_cast<u32*>(ool + (ch0 >> 1) * 4) = ll;
                bsplit2(o0[2] * inv1, o0[3] * inv1, hh, ll);
                *reinterpret_cast<u32*>(ooh + 8 * 208 + (ch0 >> 1) * 4) = hh;
                *reinterpret_cast<u32*>(ool + 8 * 208 + (ch0 >> 1) * 4) = ll;
                int ch1 = ch0 + 8;
                bsplit2(o1[0] * inv0, o1[1] * inv0, hh, ll);
                *reinterpret_cast<u32*>(ooh + (ch1 >> 1) * 4) = hh;
                *reinterpret_cast<u32*>(ool + (ch1 >> 1) * 4) = ll;
                bsplit2(o1[2] * inv1, o1[3] * inv1, hh, ll);
                *reinterpret_cast<u32*>(ooh + 8 * 208 + (ch1 >> 1) * 4) = hh;
                *reinterpret_cast<u32*>(ool + 8 * 208 + (ch1 >> 1) * 4) = ll;
            }
        }
    }

    // ---- prefetch proj_w chunk 0 ----
    float pw0[6], pw1[6];
    #pragma unroll
    for (int u = 0; u < 6; ++u) {
        pw0[u] = proj_w[(size_t)(2 * se_k2[u]) * 96 + se_n[u]];
        pw1[u] = proj_w[(size_t)(2 * se_k2[u] + 1) * 96 + se_n[u]];
    }
    __syncthreads();                      // all O writes visible

    // ---- O A-fragments into regs BEFORE W staging overwrites OW ----
    u32 oah[6][4], oal[6][4];
    {
        const u32 o_h = sb + OW_B + (u32)(m * 16 + lrow) * 208 + lkoff;
        #pragma unroll
        for (int ks = 0; ks < 6; ++ks) {
            ldmx4(oah[ks], o_h + ks * 32);
            ldmx4(oal[ks], o_h + HL + ks * 32);
        }
    }
    __syncthreads();                      // O reads done; OW safe to overwrite

    // ---- stage proj chunk 0 into buf0, prefetch chunk 1 ----
    #pragma unroll
    for (int u = 0; u < 6; ++u) {
        u32 hi, lo; bsplit2(pw0[u], pw1[u], hi, lo);
        *reinterpret_cast<u32*>(smc + OW_B + se_n[u] * 208 + se_k2[u] * 4)        = hi;
        *reinterpret_cast<u32*>(smc + OW_B + WLOF + se_n[u] * 208 + se_k2[u] * 4) = lo;
    }
    #pragma unroll
    for (int u = 0; u < 6; ++u) {
        pw0[u] = proj_w[(size_t)(2 * se_k2[u]) * 96 + 32 + se_n[u]];
        pw1[u] = proj_w[(size_t)(2 * se_k2[u] + 1) * 96 + 32 + se_n[u]];
    }
    __syncthreads();

    // ================= phase 3: proj GEMM, 3 chunks, double-buffered W ==========
    #pragma unroll 1
    for (int pc = 0; pc < 3; ++pc) {
        const u32 bb_h = b_h0 + ((pc & 1) ? HL : 0);
        const u32 bb_l = bb_h + WLOF;
        if (pc < 2) {
            const int bofs = ((pc + 1) & 1) ? HL : 0;
            #pragma unroll
            for (int u = 0; u < 6; ++u) {
                u32 hi, lo; bsplit2(pw0[u], pw1[u], hi, lo);
                *reinterpret_cast<u32*>(smc + OW_B + bofs + se_n[u] * 208 + se_k2[u] * 4)        = hi;
                *reinterpret_cast<u32*>(smc + OW_B + bofs + WLOF + se_n[u] * 208 + se_k2[u] * 4) = lo;
            }
        }
        if (pc < 1) {
            #pragma unroll
            for (int u = 0; u < 6; ++u) {
                pw0[u] = proj_w[(size_t)(2 * se_k2[u]) * 96 + 64 + se_n[u]];
                pw1[u] = proj_w[(size_t)(2 * se_k2[u] + 1) * 96 + 64 + se_n[u]];
            }
        }

        float d[2][4] = {{0.f,0.f,0.f,0.f},{0.f,0.f,0.f,0.f}};
        #pragma unroll
        for (int ks = 0; ks < 6; ++ks) {
            u32 bh[4], bl[4];
            ldmx4(bh, bb_h + ks * 32);
            ldmx4(bl, bb_l + ks * 32);
            mma16816(d[0], oah[ks], bh[0], bh[2]);
            mma16816(d[0], oah[ks], bl[0], bl[2]);
            mma16816(d[0], oal[ks], bh[0], bh[2]);
            mma16816(d[1], oah[ks], bh[1], bh[3]);
            mma16816(d[1], oah[ks], bl[1], bl[3]);
            mma16816(d[1], oal[ks], bh[1], bh[3]);
        }

        float* og = out + (size_t)blockIdx.x * 64 * 96;
        const int row0 = m * 16 + (lane >> 2);
        #pragma unroll
        for (int nt = 0; nt < 2; ++nt) {
            int g = pc * 32 + nh * 16 + nt * 8 + 2 * (lane & 3);
            float b0 = proj_b[g], b1 = proj_b[g + 1];
            float2 v0 = make_float2(d[nt][0] + b0, d[nt][1] + b1);
            float2 v1 = make_float2(d[nt][2] + b0, d[nt][3] + b1);
            *reinterpret_cast<float2*>(og + (size_t)row0 * 96 + g)       = v0;
            *reinterpret_cast<float2*>(og + (size_t)(row0 + 8) * 96 + g) = v1;
        }
        if (pc < 2) __syncthreads();
    }
}

extern "C" void kernel_launch(void* const* d_in, const int* in_sizes, int n_in,
                              void* d_out, int out_size)
{
    const float* x      = (const float*)d_in[0];
    const float* mask   = (const float*)d_in[1];
    const float* qkv_w  = (const float*)d_in[2];
    const float* qkv_b  = (const float*)d_in[3];
    const float* proj_w = (const float*)d_in[4];
    const float* proj_b = (const float*)d_in[5];
    const float* rpb    = (const float*)d_in[6];
    const int*   ridx   = (const int*)d_in[7];
    float* out = (float*)d_out;

    const int n_windows = in_sizes[0] / (NTOK * DIM);   // 8192

    cudaFuncSetAttribute(win_attn_kernel,
                         cudaFuncAttributeMaxDynamicSharedMemorySize, SMEM_BYTES);

    const int total = NW * HEADS * NTOK * NTOK;
    prep_kernel<<<(total + 255) / 256, 256>>>(rpb, ridx, mask);
    win_attn_kernel<<<n_windows, 256, SMEM_BYTES>>>(
        x, qkv_w, qkv_b, proj_w, proj_b, out);
}

// round 14
// speedup vs baseline: 1.2729x; 1.2603x over previous
#include <cuda_runtime.h>
#include <cuda_bf16.h>
#include <cstdint>

#define HEADS 6
#define NTOK  64
#define DIM   96
#define NW    512

typedef uint32_t u32;

// ---------------- bf16 split-pack: f32 pair -> (hi pair, lo pair) ----------------
__device__ __forceinline__ void bsplit2(float f0, float f1, u32& hi, u32& lo) {
    __nv_bfloat162 h = __floats2bfloat162_rn(f0, f1);
    float r0 = f0 - __bfloat162float(h.x);
    float r1 = f1 - __bfloat162float(h.y);
    __nv_bfloat162 l = __floats2bfloat162_rn(r0, r1);
    hi = ((u32)__bfloat16_as_ushort(h.y) << 16) | __bfloat16_as_ushort(h.x);
    lo = ((u32)__bfloat16_as_ushort(l.y) << 16) | __bfloat16_as_ushort(l.x);
}

// mma.m16n8k16 row.col f32 += bf16*bf16
__device__ __forceinline__ void mma16816(float* d, const u32* a, u32 b0, u32 b1) {
    asm volatile("mma.sync.aligned.m16n8k16.row.col.f32.bf16.bf16.f32 "
        "{%0,%1,%2,%3}, {%4,%5,%6,%7}, {%8,%9}, {%0,%1,%2,%3};"
        : "+f"(d[0]), "+f"(d[1]), "+f"(d[2]), "+f"(d[3])
        : "r"(a[0]), "r"(a[1]), "r"(a[2]), "r"(a[3]), "r"(b0), "r"(b1));
}
__device__ __forceinline__ void ldmx4(u32* r, u32 addr) {
    asm volatile("ldmatrix.sync.aligned.m8n8.x4.shared.b16 {%0,%1,%2,%3}, [%4];"
        : "=r"(r[0]), "=r"(r[1]), "=r"(r[2]), "=r"(r[3]) : "r"(addr));
}
__device__ __forceinline__ void ldmx4t(u32* r, u32 addr) {
    asm volatile("ldmatrix.sync.aligned.m8n8.x4.trans.shared.b16 {%0,%1,%2,%3}, [%4];"
        : "=r"(r[0]), "=r"(r[1]), "=r"(r[2]), "=r"(r[3]) : "r"(addr));
}
__device__ __forceinline__ u32 smem_u32(const void* p) {
    u32 a; asm("{ .reg .u64 t; cvta.to.shared.u64 t, %1; cvt.u32.u64 %0, t; }"
               : "=r"(a) : "l"(p)); return a;
}

// Combined (rpb-gather + shift-mask) table: [w][h][n][m] fp32, ~50MB.
__device__ float cmb[NW * HEADS * NTOK * NTOK];

__global__ void prep_kernel(const float* __restrict__ rpb,
                            const int* __restrict__ ridx,
                            const float* __restrict__ mask) {
    int i = blockIdx.x * 256 + threadIdx.x;
    if (i >= NW * HEADS * NTOK * NTOK) return;
    int w = i / (HEADS * 4096), rem = i % (HEADS * 4096);
    cmb[i] = rpb[ridx[rem % 4096] * HEADS + rem / 4096] + mask[w * 4096 + rem % 4096];
}

// ---------------- pre-split weight fragment streams (L1/L2 resident) ----------
// Index: [((c*2 + nh)*6 + ks)*32 + lane] -> uint4 = {bh0, bh1, bh2, bh3}
// where bhj = bf16 pair of W elements (k, k+1) at
//   n = c*32 + nh*16 + (j&1)*8 + (lane>>2),  k = ks*16 + ((j>>1)&1)*8 + 2*(lane&3)
// exactly matching the ldmatrix x4 mat order validated in R9.
__device__ uint4 qkvw_fh[9 * 2 * 6 * 32];   // 3456 uint4
__device__ uint4 qkvw_fl[9 * 2 * 6 * 32];
__device__ uint4 projw_fh[3 * 2 * 6 * 32];  // 1152 uint4
__device__ uint4 projw_fl[3 * 2 * 6 * 32];

__global__ void prepw_kernel(const float* __restrict__ qkv_w,
                             const float* __restrict__ proj_w) {
    int i = blockIdx.x * 256 + threadIdx.x;     // 0 .. 4607
    if (i >= 4608) return;
    bool isq = i < 3456;
    const float* W = isq ? qkv_w : proj_w;
    int idx = isq ? i : i - 3456;
    int l  = idx & 31;
    int ks = (idx >> 5) % 6;
    int nh = ((idx >> 5) / 6) & 1;
    int c  = (idx >> 5) / 12;
    int ncols = isq ? 288 : 96;
    u32 hh[4], ll[4];
    #pragma unroll
    for (int j = 0; j < 4; ++j) {
        int n = c * 32 + nh * 16 + (j & 1) * 8 + (l >> 2);
        int k = ks * 16 + ((j >> 1) & 1) * 8 + 2 * (l & 3);
        float w0 = W[(size_t)k * ncols + n];
        float w1 = W[(size_t)(k + 1) * ncols + n];
        bsplit2(w0, w1, hh[j], ll[j]);
    }
    uint4 vh = make_uint4(hh[0], hh[1], hh[2], hh[3]);
    uint4 vl = make_uint4(ll[0], ll[1], ll[2], ll[3]);
    if (isq) { qkvw_fh[idx] = vh; qkvw_fl[idx] = vl; }
    else     { projw_fh[idx] = vh; projw_fl[idx] = vl; }
}

// ---------------- SMEM layout (bytes); 208B row stride, 1 window/CTA ----------
// RQ @ 0     : x staging (hi/lo) -> overwritten by Q (hi/lo)      2x13312
// K  @ 26624 : K hi/lo                                            2x13312
// V  @ 53248 : V hi/lo                                            2x13312
// O  @ 79872 : O hi/lo (attention output)                         2x13312
#define RQ_B 0
#define KB_B 26624
#define VB_B 53248
#define OO_B 79872
#define HL   13312            // (lo - hi) offset inside each region
#define SMEM_BYTES 106496

__global__ __launch_bounds__(256, 2)
void win_attn_kernel(const float* __restrict__ x,
                     const float* __restrict__ qkv_b,
                     const float* __restrict__ proj_b,
                     float* __restrict__ out)
{
    extern __shared__ char smc[];
    const int tid  = threadIdx.x;
    const int lane = tid & 31;
    const int wid  = tid >> 5;            // 0..7
    const int m    = wid & 3;             // GEMM M-tile (16 rows of 64)
    const int nh   = wid >> 2;            // GEMM N-half of 32-col chunk

    const u32 sb = smem_u32(smc);
    const int lrow  = (lane & 7) + 8 * ((lane >> 3) & 1);
    const int lkoff = (lane >> 4) * 16;
    const u32 a_h = sb + RQ_B + (u32)(m * 16 + lrow) * 208 + lkoff;   // x / Q rows
    const u32 a_l = a_h + HL;

    // ================= phase 0: load x (64x96) into RQ, split-pack ==============
    {
        const float4* xg = reinterpret_cast<const float4*>(x + (size_t)blockIdx.x * 64 * 96);
        #pragma unroll
        for (int u = 0; u < 6; ++u) {
            int e = tid + u * 256;                 // 1536 float4
            float4 v = xg[e];
            int tok = e / 24, c4 = (e % 24) * 4;
            u32 h0, l0, h1, l1;
            bsplit2(v.x, v.y, h0, l0);
            bsplit2(v.z, v.w, h1, l1);
            *reinterpret_cast<uint2*>(smc + RQ_B + tok * 208 + c4 * 2)      = make_uint2(h0, h1);
            *reinterpret_cast<uint2*>(smc + RQ_B + HL + tok * 208 + c4 * 2) = make_uint2(l0, l1);
        }
    }
    __syncthreads();

    // ---- x A-fragments into registers (RQ region then becomes dead -> Q) ----
    u32 xah[6][4], xal[6][4];
    #pragma unroll
    for (int ks = 0; ks < 6; ++ks) {
        ldmx4(xah[ks], a_h + ks * 32);
        ldmx4(xal[ks], a_l + ks * 32);
    }

    // ================= phase 1: QKV GEMM, 9 chunks, B-frags from gmem ===========
    // No intra-loop syncs: B comes from the fragment stream; epilogue rows are
    // exclusive per warp; all cross-warp reads happen after the single sync below.
    #pragma unroll 1
    for (int c = 0; c < 9; ++c) {
        const uint4* fh = qkvw_fh + (size_t)((c * 2 + nh) * 6) * 32 + lane;
        const uint4* fl = qkvw_fl + (size_t)((c * 2 + nh) * 6) * 32 + lane;

        float d[2][4] = {{0.f,0.f,0.f,0.f},{0.f,0.f,0.f,0.f}};
        #pragma unroll
        for (int ks = 0; ks < 6; ++ks) {
            uint4 BH = fh[ks * 32];
            uint4 BL = fl[ks * 32];
            mma16816(d[0], xah[ks], BH.x, BH.z);
            mma16816(d[0], xah[ks], BL.x, BL.z);
            mma16816(d[0], xal[ks], BH.x, BH.z);
            mma16816(d[1], xah[ks], BH.y, BH.w);
            mma16816(d[1], xah[ks], BL.y, BL.w);
            mma16816(d[1], xal[ks], BH.y, BH.w);
        }

        // epilogue: +bias (Q also *0.25), split-pack into RQ/K/V [tok][ch pairs]
        const int p = c / 3;
        const int base_h = (p == 0) ? RQ_B : (p == 1) ? KB_B : VB_B;
        const int tk = m * 16 + (lane >> 2);
        char* outh = smc + base_h + tk * 208;
        char* outl = outh + HL;
        #pragma unroll
        for (int nt = 0; nt < 2; ++nt) {
            int g = c * 32 + nh * 16 + nt * 8 + 2 * (lane & 3);
            int ch = g % 96;
            float bb0 = qkv_b[g], bb1 = qkv_b[g + 1];
            float v00 = d[nt][0] + bb0, v01 = d[nt][1] + bb1;
            float v10 = d[nt][2] + bb0, v11 = d[nt][3] + bb1;
            if (p == 0) { v00 *= 0.25f; v01 *= 0.25f; v10 *= 0.25f; v11 *= 0.25f; }
            u32 hh, ll;
            bsplit2(v00, v01, hh, ll);
            *reinterpret_cast<u32*>(outh + (ch >> 1) * 4) = hh;
            *reinterpret_cast<u32*>(outl + (ch >> 1) * 4) = ll;
            bsplit2(v10, v11, hh, ll);
            *reinterpret_cast<u32*>(outh + 8 * 208 + (ch >> 1) * 4) = hh;
            *reinterpret_cast<u32*>(outl + 8 * 208 + (ch >> 1) * 4) = ll;
        }
    }
    __syncthreads();                      // Q/K/V fully written

    // ================= phase 2: attention, all-MMA, softmax in registers ========
    {
        const int hsub = wid >> 2;            // head parity
        const int mt   = wid & 3;             // 16-row q tile
        const int r    = mt * 16 + (lane >> 2);
        const float* cw = cmb + (size_t)(blockIdx.x & (NW - 1)) * (HEADS * 4096);
        const u32 qbase = sb + RQ_B + (u32)(mt * 16 + lrow) * 208 + lkoff;
        const u32 kbase = sb + KB_B + (u32)lrow * 208 + lkoff;
        const u32 vbase = sb + VB_B + (u32)lrow * 208 + lkoff;
        char* ooh = smc + OO_B + (mt * 16 + (lane >> 2)) * 208;
        char* ool = ooh + HL;

        #pragma unroll 1
        for (int hi2 = 0; hi2 < 3; ++hi2) {
            const int h = 2 * hi2 + hsub;
            const u32 chb = h * 32;

            u32 qh4[4], ql4[4];
            ldmx4(qh4, qbase + chb);
            ldmx4(ql4, qbase + HL + chb);

            float d[8][4];
            const float* cm = cw + h * 4096 + 2 * (lane & 3);
            #pragma unroll
            for (int j = 0; j < 8; ++j) {
                float2 c0 = *reinterpret_cast<const float2*>(&cm[r * 64 + 8 * j]);
                float2 c1 = *reinterpret_cast<const float2*>(&cm[(r + 8) * 64 + 8 * j]);
                d[j][0] = c0.x; d[j][1] = c0.y; d[j][2] = c1.x; d[j][3] = c1.y;
            }
            #pragma unroll
            for (int t = 0; t < 4; ++t) {
                u32 kh4[4], kl4[4];
                ldmx4(kh4, kbase + t * (16 * 208) + chb);
                ldmx4(kl4, kbase + HL + t * (16 * 208) + chb);
                mma16816(d[2 * t],     qh4, kh4[0], kh4[2]);
                mma16816(d[2 * t],     qh4, kl4[0], kl4[2]);
                mma16816(d[2 * t],     ql4, kh4[0], kh4[2]);
                mma16816(d[2 * t + 1], qh4, kh4[1], kh4[3]);
                mma16816(d[2 * t + 1], qh4, kl4[1], kl4[3]);
                mma16816(d[2 * t + 1], ql4, kh4[1], kh4[3]);
            }

            // exp WITHOUT max-shift (logits O(1); softmax shift-invariant)
            float s0 = 0.f, s1 = 0.f;
            #pragma unroll
            for (int j = 0; j < 8; ++j) {
                d[j][0] = __expf(d[j][0]); d[j][1] = __expf(d[j][1]);
                d[j][2] = __expf(d[j][2]); d[j][3] = __expf(d[j][3]);
                s0 += d[j][0] + d[j][1];
                s1 += d[j][2] + d[j][3];
            }
            s0 += __shfl_xor_sync(0xffffffffu, s0, 1, 4);
            s0 += __shfl_xor_sync(0xffffffffu, s0, 2, 4);
            s1 += __shfl_xor_sync(0xffffffffu, s1, 1, 4);
            s1 += __shfl_xor_sync(0xffffffffu, s1, 2, 4);
            const float inv0 = 1.0f / s0, inv1 = 1.0f / s1;

            // PV on unnormalized exp values
            float o0[4] = {0.f,0.f,0.f,0.f}, o1[4] = {0.f,0.f,0.f,0.f};
            #pragma unroll
            for (int ks = 0; ks < 4; ++ks) {
                u32 pah[4], pal[4];
                bsplit2(d[2*ks][0],   d[2*ks][1],   pah[0], pal[0]);
                bsplit2(d[2*ks][2],   d[2*ks][3],   pah[1], pal[1]);
                bsplit2(d[2*ks+1][0], d[2*ks+1][1], pah[2], pal[2]);
                bsplit2(d[2*ks+1][2], d[2*ks+1][3], pah[3], pal[3]);
                u32 vh4[4], vl4[4];
                ldmx4t(vh4, vbase + ks * (16 * 208) + chb);
                ldmx4t(vl4, vbase + HL + ks * (16 * 208) + chb);
                mma16816(o0, pah, vh4[0], vh4[1]);
                mma16816(o0, pah, vl4[0], vl4[1]);
                mma16816(o0, pal, vh4[0], vh4[1]);
                mma16816(o1, pah, vh4[2], vh4[3]);
                mma16816(o1, pah, vl4[2], vl4[3]);
                mma16816(o1, pal, vh4[2], vh4[3]);
            }

            {   // O into OO region, normalized here (rows r -> inv0, r+8 -> inv1)
                int ch0 = h * 16 + 2 * (lane & 3);
                u32 hh, ll;
                bsplit2(o0[0] * inv0, o0[1] * inv0, hh, ll);
                *reinterpret_cast<u32*>(ooh + (ch0 >> 1) * 4) = hh;
                *reinterpret_cast<u32*>(ool + (ch0 >> 1) * 4) = ll;
                bsplit2(o0[2] * inv1, o0[3] * inv1, hh, ll);
                *reinterpret_cast<u32*>(ooh + 8 * 208 + (ch0 >> 1) * 4) = hh;
                *reinterpret_cast<u32*>(ool + 8 * 208 + (ch0 >> 1) * 4) = ll;
                int ch1 = ch0 + 8;
                bsplit2(o1[0] * inv0, o1[1] * inv0, hh, ll);
                *reinterpret_cast<u32*>(ooh + (ch1 >> 1) * 4) = hh;
                *reinterpret_cast<u32*>(ool + (ch1 >> 1) * 4) = ll;
                bsplit2(o1[2] * inv1, o1[3] * inv1, hh, ll);
                *reinterpret_cast<u32*>(ooh + 8 * 208 + (ch1 >> 1) * 4) = hh;
                *reinterpret_cast<u32*>(ool + 8 * 208 + (ch1 >> 1) * 4) = ll;
            }
        }
    }
    __syncthreads();                      // all O writes visible

    // ---- O A-fragments into regs (O region not reused afterwards) ----
    u32 oah[6][4], oal[6][4];
    {
        const u32 o_h = sb + OO_B + (u32)(m * 16 + lrow) * 208 + lkoff;
        #pragma unroll
        for (int ks = 0; ks < 6; ++ks) {
            ldmx4(oah[ks], o_h + ks * 32);
            ldmx4(oal[ks], o_h + HL + ks * 32);
        }
    }

    // ================= phase 3: proj GEMM, 3 chunks, B-frags from gmem ==========
    #pragma unroll 1
    for (int pc = 0; pc < 3; ++pc) {
        const uint4* fh = projw_fh + (size_t)((pc * 2 + nh) * 6) * 32 + lane;
        const uint4* fl = projw_fl + (size_t)((pc * 2 + nh) * 6) * 32 + lane;

        float d[2][4] = {{0.f,0.f,0.f,0.f},{0.f,0.f,0.f,0.f}};
        #pragma unroll
        for (int ks = 0; ks < 6; ++ks) {
            uint4 BH = fh[ks * 32];
            uint4 BL = fl[ks * 32];
            mma16816(d[0], oah[ks], BH.x, BH.z);
            mma16816(d[0], oah[ks], BL.x, BL.z);
            mma16816(d[0], oal[ks], BH.x, BH.z);
            mma16816(d[1], oah[ks], BH.y, BH.w);
            mma16816(d[1], oah[ks], BL.y, BL.w);
            mma16816(d[1], oal[ks], BH.y, BH.w);
        }

        float* og = out + (size_t)blockIdx.x * 64 * 96;
        const int row0 = m * 16 + (lane >> 2);
        #pragma unroll
        for (int nt = 0; nt < 2; ++nt) {
            int g = pc * 32 + nh * 16 + nt * 8 + 2 * (lane & 3);
            float b0 = proj_b[g], b1 = proj_b[g + 1];
            float2 v0 = make_float2(d[nt][0] + b0, d[nt][1] + b1);
            float2 v1 = make_float2(d[nt][2] + b0, d[nt][3] + b1);
            *reinterpret_cast<float2*>(og + (size_t)row0 * 96 + g)       = v0;
            *reinterpret_cast<float2*>(og + (size_t)(row0 + 8) * 96 + g) = v1;
        }
    }
}

extern "C" void kernel_launch(void* const* d_in, const int* in_sizes, int n_in,
                              void* d_out, int out_size)
{
    const float* x      = (const float*)d_in[0];
    const float* mask   = (const float*)d_in[1];
    const float* qkv_w  = (const float*)d_in[2];
    const float* qkv_b  = (const float*)d_in[3];
    const float* proj_w = (const float*)d_in[4];
    const float* proj_b = (const float*)d_in[5];
    const float* rpb    = (const float*)d_in[6];
    const int*   ridx   = (const int*)d_in[7];
    float* out = (float*)d_out;

    const int n_windows = in_sizes[0] / (NTOK * DIM);   // 8192

    cudaFuncSetAttribute(win_attn_kernel,
                         cudaFuncAttributeMaxDynamicSharedMemorySize, SMEM_BYTES);

    const int total = NW * HEADS * NTOK * NTOK;
    prep_kernel<<<(total + 255) / 256, 256>>>(rpb, ridx, mask);
    prepw_kernel<<<18, 256>>>(qkv_w, proj_w);
    win_attn_kernel<<<n_windows, 256, SMEM_BYTES>>>(
        x, qkv_b, proj_b, out);
}